// round 10
// baseline (speedup 1.0000x reference)
#include <cuda_runtime.h>
#include <cuda_bf16.h>

// FilterLayer: out = irfft(rfft(x, ortho)*W, ortho) + x over last dim (L=12)
// == per-node circulant matvec: y[t] = sum_j h[n][(t-j) mod 12] * x[j],
// residual identity folded into tap d=0.
//
// R10 = R9 (PDL two-node structure, fp32 1-block build) with the apply body
// processing TWO rows per thread. nrows/2 = 3,391,488 = 207*16384, so rows
// r and r+nrows/2 share the same node: one tap fetch serves both rows,
// halving tap L1 traffic; 6 x-loads are in flight before the grid sync.

#define SEQ 12
#define NODES 207
#define NFREQ 7
#define NTAPS (NODES * SEQ)          // 2484
#define TPB 256

__device__ __align__(16) float g_H[NTAPS];

__device__ __constant__ float f_COS[12] = {
    1.0f,  0.8660254037844387f,  0.5f,  0.0f, -0.5f, -0.8660254037844387f,
   -1.0f, -0.8660254037844387f, -0.5f,  0.0f,  0.5f,  0.8660254037844387f
};
__device__ __constant__ float f_SIN[12] = {
    0.0f,  0.5f,  0.8660254037844387f,  1.0f,  0.8660254037844387f,  0.5f,
    0.0f, -0.5f, -0.8660254037844387f, -1.0f, -0.8660254037844387f, -0.5f
};

__global__ void __launch_bounds__(TPB) build_taps_kernel(
    const float* __restrict__ w /*[207][7][2]*/)
{
#if __CUDA_ARCH__ >= 900
    cudaTriggerProgrammaticLaunchCompletion();   // let apply grid dispatch now
#endif
    const int n = threadIdx.x;
    if (n >= NODES) return;

    const float* wn = w + n * (NFREQ * 2);
    const float w0  = __ldg(wn + 0);
    const float w6r = __ldg(wn + 12);
    float wr[6], wi[6];
    #pragma unroll
    for (int k = 1; k <= 5; k++) {
        wr[k] =  2.0f * __ldg(wn + 2 * k);
        wi[k] = -2.0f * __ldg(wn + 2 * k + 1);
    }
    float t[SEQ];
    #pragma unroll
    for (int d = 0; d < SEQ; d++) {
        float acc = w0 + ((d & 1) ? -w6r : w6r);
        #pragma unroll
        for (int k = 1; k <= 5; k++) {
            const int m = (k * d) % 12;            // compile-time
            acc = fmaf(wr[k], f_COS[m], acc);
            acc = fmaf(wi[k], f_SIN[m], acc);
        }
        t[d] = acc * (1.0f / 12.0f);
    }
    t[0] += 1.0f;                                  // fold residual identity

    float4* dst = reinterpret_cast<float4*>(g_H + n * SEQ);
    dst[0] = make_float4(t[0], t[1], t[2],  t[3]);
    dst[1] = make_float4(t[4], t[5], t[6],  t[7]);
    dst[2] = make_float4(t[8], t[9], t[10], t[11]);
}

__global__ void __launch_bounds__(TPB) filter_apply_kernel(
    const float4* __restrict__ x, float4* __restrict__ out, int half)
{
    const int r = blockIdx.x * TPB + threadIdx.x;   // rows r and r+half

    // 6 independent x loads issued before the PDL grid sync.
    const size_t gA = (size_t)r * 3;
    const size_t gB = (size_t)(r + half) * 3;
    const float4 a0 = __ldg(x + gA + 0);
    const float4 a1 = __ldg(x + gA + 1);
    const float4 a2 = __ldg(x + gA + 2);
    const float4 b0 = __ldg(x + gB + 0);
    const float4 b1 = __ldg(x + gB + 1);
    const float4 b2 = __ldg(x + gB + 2);

#if __CUDA_ARCH__ >= 900
    cudaGridDependencySynchronize();   // taps ready beyond this point
#endif

    // One tap fetch serves both rows (same node: half % 207 == 0).
    const int n = r % NODES;
    const float4* Hv = reinterpret_cast<const float4*>(g_H + n * SEQ);
    const float4 h0 = __ldg(Hv + 0);
    const float4 h1 = __ldg(Hv + 1);
    const float4 h2 = __ldg(Hv + 2);
    const float h[SEQ] = { h0.x, h0.y, h0.z, h0.w,
                           h1.x, h1.y, h1.z, h1.w,
                           h2.x, h2.y, h2.z, h2.w };

    // ---- row A ----
    {
        const float xv[SEQ] = { a0.x, a0.y, a0.z, a0.w,
                                a1.x, a1.y, a1.z, a1.w,
                                a2.x, a2.y, a2.z, a2.w };
        float y[SEQ];
        #pragma unroll
        for (int t = 0; t < SEQ; t++) {
            float s = 0.0f;
            #pragma unroll
            for (int j = 0; j < SEQ; j++)
                s = fmaf(h[(t - j + SEQ) % SEQ], xv[j], s);
            y[t] = s;
        }
        out[gA + 0] = make_float4(y[0], y[1], y[2],  y[3]);
        out[gA + 1] = make_float4(y[4], y[5], y[6],  y[7]);
        out[gA + 2] = make_float4(y[8], y[9], y[10], y[11]);
    }

    // ---- row B ----
    {
        const float xv[SEQ] = { b0.x, b0.y, b0.z, b0.w,
                                b1.x, b1.y, b1.z, b1.w,
                                b2.x, b2.y, b2.z, b2.w };
        float y[SEQ];
        #pragma unroll
        for (int t = 0; t < SEQ; t++) {
            float s = 0.0f;
            #pragma unroll
            for (int j = 0; j < SEQ; j++)
                s = fmaf(h[(t - j + SEQ) % SEQ], xv[j], s);
            y[t] = s;
        }
        out[gB + 0] = make_float4(y[0], y[1], y[2],  y[3]);
        out[gB + 1] = make_float4(y[4], y[5], y[6],  y[7]);
        out[gB + 2] = make_float4(y[8], y[9], y[10], y[11]);
    }
}

extern "C" void kernel_launch(void* const* d_in, const int* in_sizes, int n_in,
                              void* d_out, int out_size) {
    const float* x = (const float*)d_in[0];   // [1024,32,207,12] fp32
    const float* w = (const float*)d_in[1];   // [1,207,7,2] fp32

    build_taps_kernel<<<1, TPB>>>(w);

    const int nrows = out_size / SEQ;         // 6,782,976
    const int half  = nrows / 2;              // 3,391,488 = 207*16384 = 13248*256
    const int blocks = half / TPB;            // 13248, exact

    const float4* x4 = reinterpret_cast<const float4*>(x);
    float4* o4 = reinterpret_cast<float4*>(d_out);

    cudaLaunchConfig_t cfg = {};
    cfg.gridDim  = dim3((unsigned)blocks, 1, 1);
    cfg.blockDim = dim3(TPB, 1, 1);
    cfg.dynamicSmemBytes = 0;
    cfg.stream = 0;
    cudaLaunchAttribute attr[1];
    attr[0].id = cudaLaunchAttributeProgrammaticStreamSerialization;
    attr[0].val.programmaticStreamSerializationAllowed = 1;
    cfg.attrs = attr;
    cfg.numAttrs = 1;

    cudaError_t e = cudaLaunchKernelEx(&cfg, filter_apply_kernel, x4, o4, half);
    if (e != cudaSuccess) {
        filter_apply_kernel<<<blocks, TPB>>>(x4, o4, half);   // correct fallback
    }
}

// round 11
// speedup vs baseline: 1.1054x; 1.1054x over previous
#include <cuda_runtime.h>
#include <cuda_bf16.h>

// FilterLayer: out = irfft(rfft(x, ortho)*W, ortho) + x over last dim (L=12)
// == per-node circulant matvec: y[t] = sum_j h[n][(t-j) mod 12] * x[j],
// residual identity folded into tap d=0.
//
// R11 = R9 (best: PDL two-node, fp32 1-block build, one-row-per-thread apply
// with MLP_p1=3 — the measured-optimal shape) with two micro-levers:
//  - TPB 128 (finer CTA granularity, smoother L1tex queue / tail)
//  - streaming cache hints: __ldcs on x (read-once), __stcs on out
//    (write-once); both streams (651MB) dwarf L2 (126MB).

#define SEQ 12
#define NODES 207
#define NFREQ 7
#define NTAPS (NODES * SEQ)          // 2484
#define TPB_BUILD 256
#define TPB 128

__device__ __align__(16) float g_H[NTAPS];

__device__ __constant__ float f_COS[12] = {
    1.0f,  0.8660254037844387f,  0.5f,  0.0f, -0.5f, -0.8660254037844387f,
   -1.0f, -0.8660254037844387f, -0.5f,  0.0f,  0.5f,  0.8660254037844387f
};
__device__ __constant__ float f_SIN[12] = {
    0.0f,  0.5f,  0.8660254037844387f,  1.0f,  0.8660254037844387f,  0.5f,
    0.0f, -0.5f, -0.8660254037844387f, -1.0f, -0.8660254037844387f, -0.5f
};

__global__ void __launch_bounds__(TPB_BUILD) build_taps_kernel(
    const float* __restrict__ w /*[207][7][2]*/)
{
#if __CUDA_ARCH__ >= 900
    cudaTriggerProgrammaticLaunchCompletion();   // let apply grid dispatch now
#endif
    const int n = threadIdx.x;
    if (n >= NODES) return;

    const float* wn = w + n * (NFREQ * 2);
    const float w0  = __ldg(wn + 0);
    const float w6r = __ldg(wn + 12);
    float wr[6], wi[6];
    #pragma unroll
    for (int k = 1; k <= 5; k++) {
        wr[k] =  2.0f * __ldg(wn + 2 * k);
        wi[k] = -2.0f * __ldg(wn + 2 * k + 1);
    }
    float t[SEQ];
    #pragma unroll
    for (int d = 0; d < SEQ; d++) {
        float acc = w0 + ((d & 1) ? -w6r : w6r);
        #pragma unroll
        for (int k = 1; k <= 5; k++) {
            const int m = (k * d) % 12;            // compile-time
            acc = fmaf(wr[k], f_COS[m], acc);
            acc = fmaf(wi[k], f_SIN[m], acc);
        }
        t[d] = acc * (1.0f / 12.0f);
    }
    t[0] += 1.0f;                                  // fold residual identity

    float4* dst = reinterpret_cast<float4*>(g_H + n * SEQ);
    dst[0] = make_float4(t[0], t[1], t[2],  t[3]);
    dst[1] = make_float4(t[4], t[5], t[6],  t[7]);
    dst[2] = make_float4(t[8], t[9], t[10], t[11]);
}

__global__ void __launch_bounds__(TPB) filter_apply_kernel(
    const float4* __restrict__ x, float4* __restrict__ out)
{
    const int r = blockIdx.x * TPB + threadIdx.x;   // one row per thread

    // x loads are independent of the build kernel — issue before grid sync.
    // Read-once stream: evict-first.
    const size_t g = (size_t)r * 3;
    const float4 a = __ldcs(x + g + 0);
    const float4 b = __ldcs(x + g + 1);
    const float4 c = __ldcs(x + g + 2);

#if __CUDA_ARCH__ >= 900
    cudaGridDependencySynchronize();   // taps ready beyond this point
#endif

    const int n = r % NODES;
    const float4* Hv = reinterpret_cast<const float4*>(g_H + n * SEQ);
    const float4 h0 = __ldg(Hv + 0);
    const float4 h1 = __ldg(Hv + 1);
    const float4 h2 = __ldg(Hv + 2);
    const float h[SEQ] = { h0.x, h0.y, h0.z, h0.w,
                           h1.x, h1.y, h1.z, h1.w,
                           h2.x, h2.y, h2.z, h2.w };

    const float xv[SEQ] = { a.x, a.y, a.z, a.w,
                            b.x, b.y, b.z, b.w,
                            c.x, c.y, c.z, c.w };

    float y[SEQ];
    #pragma unroll
    for (int t = 0; t < SEQ; t++) {
        float s = 0.0f;
        #pragma unroll
        for (int j = 0; j < SEQ; j++)
            s = fmaf(h[(t - j + SEQ) % SEQ], xv[j], s);   // compile-time index
        y[t] = s;
    }

    // Write-once stream: evict-first.
    __stcs(out + g + 0, make_float4(y[0], y[1], y[2],  y[3]));
    __stcs(out + g + 1, make_float4(y[4], y[5], y[6],  y[7]));
    __stcs(out + g + 2, make_float4(y[8], y[9], y[10], y[11]));
}

extern "C" void kernel_launch(void* const* d_in, const int* in_sizes, int n_in,
                              void* d_out, int out_size) {
    const float* x = (const float*)d_in[0];   // [1024,32,207,12] fp32
    const float* w = (const float*)d_in[1];   // [1,207,7,2] fp32

    build_taps_kernel<<<1, TPB_BUILD>>>(w);

    const int nrows = out_size / SEQ;         // 6,782,976 = 52992 * 128 exactly
    const int blocks = nrows / TPB;

    const float4* x4 = reinterpret_cast<const float4*>(x);
    float4* o4 = reinterpret_cast<float4*>(d_out);

    // PDL launch: apply grid may begin dispatch while build runs; the
    // device-side cudaGridDependencySynchronize provides ordering.
    cudaLaunchConfig_t cfg = {};
    cfg.gridDim  = dim3((unsigned)blocks, 1, 1);
    cfg.blockDim = dim3(TPB, 1, 1);
    cfg.dynamicSmemBytes = 0;
    cfg.stream = 0;
    cudaLaunchAttribute attr[1];
    attr[0].id = cudaLaunchAttributeProgrammaticStreamSerialization;
    attr[0].val.programmaticStreamSerializationAllowed = 1;
    cfg.attrs = attr;
    cfg.numAttrs = 1;

    cudaError_t e = cudaLaunchKernelEx(&cfg, filter_apply_kernel, x4, o4);
    if (e != cudaSuccess) {
        filter_apply_kernel<<<blocks, TPB>>>(x4, o4);   // correct fallback
    }
}